// round 15
// baseline (speedup 1.0000x reference)
#include <cuda_runtime.h>
#include <cuda_fp16.h>
#include <cuda_bf16.h>
#include <cstdint>

// Problem-fixed maxima: N=20000, E=320000, F up to 512
#define MAXN 20000
#define MAXE 320000
#define MAXF 512

// -------- scratch (static device memory; no allocations allowed) --------
__device__ int    g_indeg[MAXN];
__device__ float  g_dis[MAXN];
__device__ int    g_offsets[MAXN + 1];
__device__ int    g_cursor[MAXN];
__device__ int    g_part[128];
__device__ int2   g_csr[MAXE];        // .x = src, .y = bitcast(norm)
__device__ float  g_h0[(size_t)MAXN * MAXF];
__device__ float  g_h1[(size_t)MAXN * MAXF];
__device__ __half g_Ahi[(size_t)MAXN * MAXF];
__device__ __half g_Alo[(size_t)MAXN * MAXF];
__device__ __half g_Chi[(size_t)MAXN * MAXF];
__device__ __half g_Clo[(size_t)MAXN * MAXF];
__device__ __half g_Bhi[(size_t)MAXF * MAXF];
__device__ __half g_Blo[(size_t)MAXF * MAXF];

__device__ __forceinline__ uint32_t smem_u32(const void* p) {
    uint32_t a;
    asm("{ .reg .u64 t; cvta.to.shared.u64 t, %1; cvt.u32.u64 %0, t; }" : "=r"(a) : "l"(p));
    return a;
}
__device__ __forceinline__ void ldsm_x4(uint32_t& r0, uint32_t& r1, uint32_t& r2, uint32_t& r3,
                                        uint32_t addr) {
    asm volatile("ldmatrix.sync.aligned.m8n8.x4.shared.b16 {%0,%1,%2,%3}, [%4];"
                 : "=r"(r0), "=r"(r1), "=r"(r2), "=r"(r3) : "r"(addr));
}
__device__ __forceinline__ void mma16816(float* c, uint32_t a0, uint32_t a1, uint32_t a2,
                                         uint32_t a3, uint32_t b0, uint32_t b1) {
    asm volatile(
        "mma.sync.aligned.m16n8k16.row.col.f32.f16.f16.f32 "
        "{%0,%1,%2,%3}, {%4,%5,%6,%7}, {%8,%9}, {%0,%1,%2,%3};"
        : "+f"(c[0]), "+f"(c[1]), "+f"(c[2]), "+f"(c[3])
        : "r"(a0), "r"(a1), "r"(a2), "r"(a3), "r"(b0), "r"(b1));
}
__device__ __forceinline__ void cp16(uint32_t saddr, const void* g, bool v) {
    asm volatile("cp.async.cg.shared.global [%0], [%1], 16, %2;"
                 :: "r"(saddr), "l"(g), "r"(v ? 16 : 0) : "memory");
}
__device__ __forceinline__ void cp_commit() {
    asm volatile("cp.async.commit_group;" ::: "memory");
}
template <int NN>
__device__ __forceinline__ void cp_wait() {
    asm volatile("cp.async.wait_group %0;" :: "n"(NN) : "memory");
}
__device__ __forceinline__ __half2 split_hi2(float a, float b, __half2& lo2) {
    __half ha = __float2half_rn(a), hb = __float2half_rn(b);
    lo2 = __halves2half2(__float2half_rn(a - __half2float(ha)),
                         __float2half_rn(b - __half2float(hb)));
    return __halves2half2(ha, hb);
}

// ---------------- preprocessing ----------------
__global__ void zero_indeg_kernel(int n) {
    int i = blockIdx.x * blockDim.x + threadIdx.x;
    if (i < n) g_indeg[i] = 0;
}
__global__ void count_indeg_kernel(const int* __restrict__ dst, int e) {
    int i = blockIdx.x * blockDim.x + threadIdx.x;
    if (i < e) atomicAdd(&g_indeg[dst[i]], 1);
}

// ---- grid-wide 3-phase exclusive scan of g_indeg -> g_offsets/g_cursor ----
__global__ void scan_part_kernel(int n) {
    const int tid = threadIdx.x;
    const int i = blockIdx.x * 256 + tid;
    int v = 0;
    if (i < n) {
        v = g_indeg[i];
        g_dis[i] = rsqrtf((float)(v + 1));   // +1 self-loop
    }
    int r = v;
    const int lane = tid & 31, w = tid >> 5;
    #pragma unroll
    for (int o = 16; o > 0; o >>= 1) r += __shfl_xor_sync(~0u, r, o);
    __shared__ int ws[8];
    if (lane == 0) ws[w] = r;
    __syncthreads();
    if (tid == 0) {
        int s = 0;
        #pragma unroll
        for (int k = 0; k < 8; k++) s += ws[k];
        g_part[blockIdx.x] = s;
    }
}
__global__ void scan_bsum_kernel(int nb, int n) {
    const int tid = threadIdx.x;   // 128
    int v = (tid < nb) ? g_part[tid] : 0;
    const int lane = tid & 31, w = tid >> 5;
    int inc = v;
    #pragma unroll
    for (int o = 1; o < 32; o <<= 1) { int t = __shfl_up_sync(~0u, inc, o); if (lane >= o) inc += t; }
    __shared__ int ws[4];
    if (lane == 31) ws[w] = inc;
    __syncthreads();
    if (tid == 0) {
        int run = 0;
        #pragma unroll
        for (int k = 0; k < 4; k++) { int t = ws[k]; ws[k] = run; run += t; }
    }
    __syncthreads();
    int excl = ws[w] + inc - v;
    if (tid < nb) g_part[tid] = excl;
    if (tid == nb - 1) g_offsets[n] = excl + v;
}
__global__ void scan_emit_kernel(int n) {
    const int tid = threadIdx.x;
    const int i = blockIdx.x * 256 + tid;
    int v = (i < n) ? g_indeg[i] : 0;
    const int lane = tid & 31, w = tid >> 5;
    int inc = v;
    #pragma unroll
    for (int o = 1; o < 32; o <<= 1) { int t = __shfl_up_sync(~0u, inc, o); if (lane >= o) inc += t; }
    __shared__ int ws[8];
    if (lane == 31) ws[w] = inc;
    __syncthreads();
    if (tid == 0) {
        int run = 0;
        #pragma unroll
        for (int k = 0; k < 8; k++) { int t = ws[k]; ws[k] = run; run += t; }
    }
    __syncthreads();
    if (i < n) {
        int off = g_part[blockIdx.x] + ws[w] + inc - v;
        g_offsets[i] = off;
        g_cursor[i]  = off;
    }
}

__global__ void fill_csr_kernel(const int* __restrict__ src, const int* __restrict__ dst, int e) {
    int i = blockIdx.x * blockDim.x + threadIdx.x;
    if (i < e) {
        int s = src[i], d = dst[i];
        int pos = atomicAdd(&g_cursor[d], 1);
        g_csr[pos] = make_int2(s, __float_as_int(g_dis[s] * g_dis[d]));
    }
}

// -------- ALL weights [K,N] row-major -> Bt [N,K] fp16 hi/lo split, ONE kernel --------
__global__ void wsplit_all_kernel(const float* __restrict__ W1, const float* __restrict__ W2,
                                  const float* __restrict__ W3,
                                  __half* __restrict__ bhi, __half* __restrict__ blo) {
    __shared__ float tile[32][33];
    const int b = blockIdx.x;
    const float* W; __half *hi, *lo; int K, N, t;
    if (b < 64)       { W = W1; hi = bhi;          lo = blo;          K = 128; N = 512; t = b; }
    else if (b < 192) { W = W2; hi = bhi + 65536;  lo = blo + 65536;  K = 512; N = 256; t = b - 64; }
    else              { W = W3; hi = bhi + 196608; lo = blo + 196608; K = 256; N = 128; t = b - 192; }
    const int ntx = N >> 5;
    const int bx = (t % ntx) * 32;   // N origin
    const int by = (t / ntx) * 32;   // K origin
    const int tx = threadIdx.x & 31, ty = threadIdx.x >> 5;
    #pragma unroll
    for (int r = 0; r < 32; r += 8)
        tile[ty + r][tx] = W[(size_t)(by + ty + r) * N + bx + tx];
    __syncthreads();
    #pragma unroll
    for (int r = 0; r < 32; r += 8) {
        float f = tile[tx][ty + r];
        __half h = __float2half_rn(f);
        size_t o = (size_t)(bx + ty + r) * K + by + tx;
        hi[o] = h;
        lo[o] = __float2half_rn(f - __half2float(h));
    }
}

// ============ HMMA fp16-split GEMM, cp.async 2-stage pipeline (BM=128) ============
#define BM 128
#define BN 128
#define BK 32
#define ASTR 40                      // halves per row (padded): 80 bytes
#define TILE_B 10240                 // 128*80 bytes per tile
#define STAGE_B (4 * TILE_B)         // AH AL BH BL
#define GEMM_SMEM (2 * STAGE_B)      // 81920 bytes

template <int EPI>
__global__ void __launch_bounds__(256)
gemm_hmma_kernel(const __half* __restrict__ Ahi, const __half* __restrict__ Alo,
                 const __half* __restrict__ Bhi, const __half* __restrict__ Blo,
                 float* __restrict__ Cf, __half* __restrict__ Chi, __half* __restrict__ Clo,
                 const float* __restrict__ bias, int M, int N, int K) {
    extern __shared__ char smem[];
    const uint32_t sb = smem_u32(smem);

    const int tid = threadIdx.x;
    const int lane = tid & 31, wid = tid >> 5;
    const int wm = wid & 1;        // 0..1 (m)
    const int wn = wid >> 1;       // 0..3 (n)
    const int by = blockIdx.y;
    const int n0 = blockIdx.x * BN;

    float acc[4][4][4];
    #pragma unroll
    for (int mt = 0; mt < 4; mt++)
        #pragma unroll
        for (int nt = 0; nt < 4; nt++)
            #pragma unroll
            for (int r = 0; r < 4; r++) acc[mt][nt][r] = 0.f;

    const int a_msel = lane >> 3;
    const int a_rowin = (lane & 7) + ((a_msel & 1) << 3);
    const int a_colin = (a_msel >> 1) << 3;
    // B ldsm_x4 addressing: lanes 0-15 -> first n8 tile (two k halves),
    // lanes 16-31 -> second n8 tile.
    const int b_rowin4 = ((lane >> 4) << 3) + (lane & 7);
    const int b_colin4 = ((lane >> 3) & 1) << 3;

    const int ldrow = tid >> 2;          // 0..63
    const int ldsegB = (tid & 3) * 16;
    const int ldsegH = (tid & 3) * 8;

    auto load_stage = [&](int s, int k0) {
        const uint32_t st = sb + s * STAGE_B;
        #pragma unroll
        for (int h = 0; h < 2; h++) {
            const int row = ldrow + h * 64;
            const int ar = by * BM + row;
            const bool va = (ar < M);
            const int arc = va ? ar : 0;
            const uint32_t so = st + row * 80 + ldsegB;
            size_t ai = (size_t)arc * K + k0 + ldsegH;
            cp16(so,              Ahi + ai, va);
            cp16(so + TILE_B,     Alo + ai, va);
            size_t bi = (size_t)(n0 + row) * K + k0 + ldsegH;
            cp16(so + 2 * TILE_B, Bhi + bi, true);
            cp16(so + 3 * TILE_B, Blo + bi, true);
        }
        cp_commit();
    };

    const int nc = K / BK;
    load_stage(0, 0);

    for (int c = 0; c < nc; c++) {
        cp_wait<0>();
        __syncthreads();
        if (c + 1 < nc) load_stage((c + 1) & 1, (c + 1) * BK);

        const uint32_t st = sb + (c & 1) * STAGE_B;
        const uint32_t aAh = st;
        const uint32_t aAl = st + TILE_B;
        const uint32_t aBh = st + 2 * TILE_B;
        const uint32_t aBl = st + 3 * TILE_B;

        #pragma unroll
        for (int ks = 0; ks < 2; ks++) {
            uint32_t bh[4][2], bl[4][2];
            #pragma unroll
            for (int ntp = 0; ntp < 2; ntp++) {   // pair of n8 tiles per ldsm_x4
                uint32_t boff = ((wn * 32 + ntp * 16 + b_rowin4) * ASTR + ks * 16 + b_colin4) * 2;
                ldsm_x4(bh[2 * ntp][0], bh[2 * ntp][1],
                        bh[2 * ntp + 1][0], bh[2 * ntp + 1][1], aBh + boff);
                ldsm_x4(bl[2 * ntp][0], bl[2 * ntp][1],
                        bl[2 * ntp + 1][0], bl[2 * ntp + 1][1], aBl + boff);
            }
            #pragma unroll
            for (int mt = 0; mt < 4; mt++) {
                uint32_t aoff = ((wm * 64 + mt * 16 + a_rowin) * ASTR + ks * 16 + a_colin) * 2;
                uint32_t ah0, ah1, ah2, ah3, al0, al1, al2, al3;
                ldsm_x4(ah0, ah1, ah2, ah3, aAh + aoff);
                ldsm_x4(al0, al1, al2, al3, aAl + aoff);
                #pragma unroll
                for (int nt = 0; nt < 4; nt++) {
                    mma16816(acc[mt][nt], ah0, ah1, ah2, ah3, bh[nt][0], bh[nt][1]);
                    mma16816(acc[mt][nt], ah0, ah1, ah2, ah3, bl[nt][0], bl[nt][1]);
                    mma16816(acc[mt][nt], al0, al1, al2, al3, bh[nt][0], bh[nt][1]);
                }
            }
        }
        __syncthreads();
    }

    const int erow = lane >> 2;
    const int ecol = (lane & 3) << 1;
    #pragma unroll
    for (int mt = 0; mt < 4; mt++) {
        #pragma unroll
        for (int nt = 0; nt < 4; nt++) {
            const int gc = n0 + wn * 32 + nt * 8 + ecol;
            #pragma unroll
            for (int half = 0; half < 2; half++) {
                const int gr = by * BM + wm * 64 + mt * 16 + erow + half * 8;
                if (gr < M) {
                    float v0 = acc[mt][nt][half * 2 + 0];
                    float v1 = acc[mt][nt][half * 2 + 1];
                    if (EPI == 1) {
                        v0 += bias[gc];     v1 += bias[gc + 1];
                        v0 = (v0 > 0.f) ? v0 : 0.15f * v0;
                        v1 = (v1 > 0.f) ? v1 : 0.15f * v1;
                        __half2 lo2;
                        __half2 hi2 = split_hi2(v0, v1, lo2);
                        size_t o = (size_t)gr * N + gc;
                        *(__half2*)(Chi + o) = hi2;
                        *(__half2*)(Clo + o) = lo2;
                    } else {
                        *(float2*)(Cf + (size_t)gr * N + gc) = make_float2(v0, v1);
                    }
                }
            }
        }
    }
}

// ============ BM=64 variant, generalized N tiles: grid (N/128, M/64) ============
#define T64_A 5120                    // 64*80
#define T64_B 10240                   // 128*80
#define STAGE64 (2 * T64_A + 2 * T64_B)   // 30720
#define GEMM64_SMEM (2 * STAGE64)         // 61440

__global__ void __launch_bounds__(256)
gemm_hmma64_kernel(const __half* __restrict__ Ahi, const __half* __restrict__ Alo,
                   const __half* __restrict__ Bhi, const __half* __restrict__ Blo,
                   float* __restrict__ Cf, int M, int N, int K) {
    extern __shared__ char smem[];
    const uint32_t sb = smem_u32(smem);

    const int tid = threadIdx.x;
    const int lane = tid & 31, wid = tid >> 5;   // wn = wid (0..7), 16 cols each
    const int by = blockIdx.y;                   // 64-row tile
    const int n0 = blockIdx.x * 128;             // 128-col tile

    float acc[4][2][4];
    #pragma unroll
    for (int mt = 0; mt < 4; mt++)
        #pragma unroll
        for (int nt = 0; nt < 2; nt++)
            #pragma unroll
            for (int r = 0; r < 4; r++) acc[mt][nt][r] = 0.f;

    const int a_msel = lane >> 3;
    const int a_rowin = (lane & 7) + ((a_msel & 1) << 3);
    const int a_colin = (a_msel >> 1) << 3;
    const int b_rowin4 = ((lane >> 4) << 3) + (lane & 7);
    const int b_colin4 = ((lane >> 3) & 1) << 3;

    const int ldrow = tid >> 2;          // 0..63
    const int ldsegB = (tid & 3) * 16;
    const int ldsegH = (tid & 3) * 8;

    auto load_stage = [&](int s, int k0) {
        const uint32_t st = sb + s * STAGE64;
        {
            const int ar = by * 64 + ldrow;
            const bool va = (ar < M);
            const int arc = va ? ar : 0;
            const uint32_t so = st + ldrow * 80 + ldsegB;
            size_t ai = (size_t)arc * K + k0 + ldsegH;
            cp16(so,         Ahi + ai, va);
            cp16(so + T64_A, Alo + ai, va);
        }
        #pragma unroll
        for (int h = 0; h < 2; h++) {
            const int row = ldrow + h * 64;
            const uint32_t so = st + 2 * T64_A + row * 80 + ldsegB;
            size_t bi = (size_t)(n0 + row) * K + k0 + ldsegH;
            cp16(so,         Bhi + bi, true);
            cp16(so + T64_B, Blo + bi, true);
        }
        cp_commit();
    };

    const int nc = K / BK;
    load_stage(0, 0);

    for (int c = 0; c < nc; c++) {
        cp_wait<0>();
        __syncthreads();
        if (c + 1 < nc) load_stage((c + 1) & 1, (c + 1) * BK);

        const uint32_t st = sb + (c & 1) * STAGE64;
        const uint32_t aAh = st;
        const uint32_t aAl = st + T64_A;
        const uint32_t aBh = st + 2 * T64_A;
        const uint32_t aBl = st + 2 * T64_A + T64_B;

        #pragma unroll
        for (int ks = 0; ks < 2; ks++) {
            uint32_t bh[2][2], bl[2][2];
            {   // one ldsm_x4 covers both n8 tiles of this warp
                uint32_t boff = ((wid * 16 + b_rowin4) * ASTR + ks * 16 + b_colin4) * 2;
                ldsm_x4(bh[0][0], bh[0][1], bh[1][0], bh[1][1], aBh + boff);
                ldsm_x4(bl[0][0], bl[0][1], bl[1][0], bl[1][1], aBl + boff);
            }
            #pragma unroll
            for (int mt = 0; mt < 4; mt++) {
                uint32_t aoff = ((mt * 16 + a_rowin) * ASTR + ks * 16 + a_colin) * 2;
                uint32_t ah0, ah1, ah2, ah3, al0, al1, al2, al3;
                ldsm_x4(ah0, ah1, ah2, ah3, aAh + aoff);
                ldsm_x4(al0, al1, al2, al3, aAl + aoff);
                #pragma unroll
                for (int nt = 0; nt < 2; nt++) {
                    mma16816(acc[mt][nt], ah0, ah1, ah2, ah3, bh[nt][0], bh[nt][1]);
                    mma16816(acc[mt][nt], ah0, ah1, ah2, ah3, bl[nt][0], bl[nt][1]);
                    mma16816(acc[mt][nt], al0, al1, al2, al3, bh[nt][0], bh[nt][1]);
                }
            }
        }
        __syncthreads();
    }

    const int erow = lane >> 2;
    const int ecol = (lane & 3) << 1;
    #pragma unroll
    for (int mt = 0; mt < 4; mt++) {
        #pragma unroll
        for (int nt = 0; nt < 2; nt++) {
            const int gc = n0 + wid * 16 + nt * 8 + ecol;
            #pragma unroll
            for (int half = 0; half < 2; half++) {
                const int gr = by * 64 + mt * 16 + erow + half * 8;
                if (gr < M) {
                    *(float2*)(Cf + (size_t)gr * N + gc) =
                        make_float2(acc[mt][nt][half * 2 + 0], acc[mt][nt][half * 2 + 1]);
                }
            }
        }
    }
}

// ------- aggregation (warp per node, float4): out = [lrelu(]sum + self[+bias)] -------
template <int F, int OUT_SPLIT, int BIASACT>
__global__ void __launch_bounds__(256)
agg_warp_kernel(const float* __restrict__ h, float* __restrict__ outf,
                __half* __restrict__ ohi, __half* __restrict__ olo,
                const float* __restrict__ bias, int n) {
    const int gw = (blockIdx.x * blockDim.x + threadIdx.x) >> 5;
    const int lane = threadIdx.x & 31;
    if (gw >= n) return;
    constexpr int V = F / 128;

    float4 acc[V];
    const float di = g_dis[gw];
    const float selfw = di * di;
    const float4* hrow = (const float4*)(h + (size_t)gw * F);
    #pragma unroll
    for (int v = 0; v < V; v++) {
        float4 t = hrow[lane + 32 * v];
        acc[v] = make_float4(selfw * t.x, selfw * t.y, selfw * t.z, selfw * t.w);
    }

    const int beg = g_offsets[gw];
    const int end = g_offsets[gw + 1];
    for (int j = beg; j < end; j++) {
        const int2  c = g_csr[j];
        const int   s = c.x;
        const float w = __int_as_float(c.y);
        const float4* hs = (const float4*)(h + (size_t)s * F);
        #pragma unroll
        for (int v = 0; v < V; v++) {
            float4 t = hs[lane + 32 * v];
            acc[v].x += w * t.x; acc[v].y += w * t.y;
            acc[v].z += w * t.z; acc[v].w += w * t.w;
        }
    }

    #pragma unroll
    for (int v = 0; v < V; v++) {
        float4 r = acc[v];
        if (BIASACT) {
            const float4 b = ((const float4*)bias)[lane + 32 * v];
            r.x += b.x; r.y += b.y; r.z += b.z; r.w += b.w;
            r.x = (r.x > 0.f) ? r.x : 0.15f * r.x;
            r.y = (r.y > 0.f) ? r.y : 0.15f * r.y;
            r.z = (r.z > 0.f) ? r.z : 0.15f * r.z;
            r.w = (r.w > 0.f) ? r.w : 0.15f * r.w;
        }
        const size_t o = (size_t)gw * F + (lane + 32 * v) * 4;
        if (OUT_SPLIT) {
            __half2 lo0, lo1;
            __half2 hi0 = split_hi2(r.x, r.y, lo0);
            __half2 hi1 = split_hi2(r.z, r.w, lo1);
            *(__half2*)(ohi + o)     = hi0;
            *(__half2*)(ohi + o + 2) = hi1;
            *(__half2*)(olo + o)     = lo0;
            *(__half2*)(olo + o + 2) = lo1;
        } else {
            *(float4*)(outf + o) = r;
        }
    }
}

// ---------------- fused head: h(128) -> 16 -> lrelu(32) -> 2 ----------------
__global__ __launch_bounds__(256)
void head_kernel(const float* __restrict__ h,
                 const float* __restrict__ Wp,  const float* __restrict__ bp,
                 const float* __restrict__ Wf1, const float* __restrict__ bf1,
                 const float* __restrict__ Wf2, const float* __restrict__ bf2,
                 float* __restrict__ out, int n) {
    __shared__ float sWp[128 * 16];
    __shared__ float sWf1[16 * 32];
    __shared__ float sWf2[32 * 2];
    __shared__ float sbp[16], sbf1[32], sbf2[2];

    for (int i = threadIdx.x; i < 128 * 16; i += 256) sWp[i] = Wp[i];
    for (int i = threadIdx.x; i < 16 * 32;  i += 256) sWf1[i] = Wf1[i];
    if (threadIdx.x < 64) sWf2[threadIdx.x] = Wf2[threadIdx.x];
    if (threadIdx.x < 16) sbp[threadIdx.x]  = bp[threadIdx.x];
    if (threadIdx.x < 32) sbf1[threadIdx.x] = bf1[threadIdx.x];
    if (threadIdx.x < 2)  sbf2[threadIdx.x] = bf2[threadIdx.x];
    __syncthreads();

    const int warp = threadIdx.x / 32, lane = threadIdx.x % 32;
    const int node = blockIdx.x * 8 + warp;
    if (node >= n) return;

    float hv[4];
    const float* hr = h + (size_t)node * 128;
    #pragma unroll
    for (int k = 0; k < 4; k++) hv[k] = hr[lane + 32 * k];

    float s16[16];
    #pragma unroll
    for (int j = 0; j < 16; j++) {
        float p = 0.f;
        #pragma unroll
        for (int k = 0; k < 4; k++) p += hv[k] * sWp[(lane + 32 * k) * 16 + j];
        #pragma unroll
        for (int o = 16; o > 0; o >>= 1) p += __shfl_xor_sync(0xffffffffu, p, o);
        s16[j] = p + sbp[j];
    }

    float tv = sbf1[lane];
    #pragma unroll
    for (int k = 0; k < 16; k++) tv += s16[k] * sWf1[k * 32 + lane];
    tv = (tv > 0.f) ? tv : 0.15f * tv;

    float v0 = tv * sWf2[lane * 2 + 0];
    float v1 = tv * sWf2[lane * 2 + 1];
    #pragma unroll
    for (int o = 16; o > 0; o >>= 1) {
        v0 += __shfl_xor_sync(0xffffffffu, v0, o);
        v1 += __shfl_xor_sync(0xffffffffu, v1, o);
    }
    if (lane == 0) {
        out[(size_t)node * 2 + 0] = v0 + sbf2[0];
        out[(size_t)node * 2 + 1] = v1 + sbf2[1];
    }
}

// ---------------- launch ----------------
extern "C" void kernel_launch(void* const* d_in, const int* in_sizes, int n_in,
                              void* d_out, int out_size) {
    const float* x   = (const float*)d_in[0];
    const int*   ei  = (const int*)  d_in[1];
    const float* W1  = (const float*)d_in[3];
    const float* b1  = (const float*)d_in[4];
    const float* W2  = (const float*)d_in[5];
    const float* b2  = (const float*)d_in[6];
    const float* W3  = (const float*)d_in[7];
    const float* b3  = (const float*)d_in[8];
    const float* Wp  = (const float*)d_in[9];
    const float* bp  = (const float*)d_in[10];
    const float* Wf1 = (const float*)d_in[11];
    const float* bf1 = (const float*)d_in[12];
    const float* Wf2 = (const float*)d_in[13];
    const float* bf2 = (const float*)d_in[14];
    float* out = (float*)d_out;

    const int N = in_sizes[0] / 128;
    const int E = in_sizes[1] / 2;
    const int* src = ei;
    const int* dst = ei + E;

    float *h0, *h1;
    __half *ahi, *alo, *chi, *clo, *bhi, *blo;
    cudaGetSymbolAddress((void**)&h0, g_h0);
    cudaGetSymbolAddress((void**)&h1, g_h1);
    cudaGetSymbolAddress((void**)&ahi, g_Ahi);
    cudaGetSymbolAddress((void**)&alo, g_Alo);
    cudaGetSymbolAddress((void**)&chi, g_Chi);
    cudaGetSymbolAddress((void**)&clo, g_Clo);
    cudaGetSymbolAddress((void**)&bhi, g_Bhi);
    cudaGetSymbolAddress((void**)&blo, g_Blo);

    __half *b1hi = bhi,          *b1lo = blo;            // 128*512
    __half *b2hi = bhi + 65536,  *b2lo = blo + 65536;    // 512*256
    __half *b3hi = bhi + 196608, *b3lo = blo + 196608;   // 256*128

    cudaFuncSetAttribute(gemm_hmma_kernel<0>,
                         cudaFuncAttributeMaxDynamicSharedMemorySize, GEMM_SMEM);
    cudaFuncSetAttribute(gemm_hmma_kernel<1>,
                         cudaFuncAttributeMaxDynamicSharedMemorySize, GEMM_SMEM);
    cudaFuncSetAttribute(gemm_hmma64_kernel,
                         cudaFuncAttributeMaxDynamicSharedMemorySize, GEMM64_SMEM);

    const int GM = (N + 127) / 128;
    const int GM64 = (N + 63) / 64;
    const int AGG_BLK = (N * 32 + 255) / 256;
    const int NB = (N + 255) / 256;   // scan blocks (<=128)

    // --- preprocessing ---
    zero_indeg_kernel<<<(N + 255) / 256, 256>>>(N);
    count_indeg_kernel<<<(E + 255) / 256, 256>>>(dst, E);
    scan_part_kernel<<<NB, 256>>>(N);
    scan_bsum_kernel<<<1, 128>>>(NB, N);
    scan_emit_kernel<<<NB, 256>>>(N);
    fill_csr_kernel<<<(E + 255) / 256, 256>>>(src, dst, E);

    // --- layer 1 (aggregate-first): split(agg(x)) -> gemm(+bias+lrelu, split out) ---
    agg_warp_kernel<128, 1, 0><<<AGG_BLK, 256>>>(x, nullptr, ahi, alo, nullptr, N);
    wsplit_all_kernel<<<224, 256>>>(W1, W2, W3, bhi, blo);
    {
        dim3 grid(512 / 128, GM);
        gemm_hmma_kernel<1><<<grid, 256, GEMM_SMEM>>>(ahi, alo, b1hi, b1lo, nullptr,
                                                      chi, clo, b1, N, 512, 128);
    }
    // --- layer 2: BM=64 gemm -> agg(+bias+lrelu, split) ---
    {
        dim3 grid(256 / 128, GM64);
        gemm_hmma64_kernel<<<grid, 256, GEMM64_SMEM>>>(chi, clo, b2hi, b2lo, h0,
                                                       N, 256, 512);
        agg_warp_kernel<256, 1, 1><<<AGG_BLK, 256>>>(h0, nullptr, ahi, alo, b2, N);
    }
    // --- layer 3: BM=64 gemm -> agg(+bias+lrelu, fp32) -> head ---
    {
        dim3 grid(1, GM64);
        gemm_hmma64_kernel<<<grid, 256, GEMM64_SMEM>>>(ahi, alo, b3hi, b3lo, h0,
                                                       N, 128, 256);
        agg_warp_kernel<128, 0, 1><<<AGG_BLK, 256>>>(h0, h1, nullptr, nullptr, b3, N);
    }
    head_kernel<<<(N + 7) / 8, 256>>>(h1, Wp, bp, Wf1, bf1, Wf2, bf2, out, N);
}

// round 16
// speedup vs baseline: 1.0281x; 1.0281x over previous
#include <cuda_runtime.h>
#include <cuda_fp16.h>
#include <cuda_bf16.h>
#include <cstdint>

// Problem-fixed maxima: N=20000, E=320000, F up to 512
#define MAXN 20000
#define MAXE 320000
#define MAXF 512

// -------- scratch (static device memory; no allocations allowed) --------
__device__ int    g_indeg[MAXN];
__device__ float  g_dis[MAXN];
__device__ int    g_offsets[MAXN + 1];
__device__ int    g_cursor[MAXN];
__device__ int    g_part[128];
__device__ int2   g_csr[MAXE];        // .x = src, .y = bitcast(norm)
__device__ float  g_h0[(size_t)MAXN * MAXF];
__device__ float  g_h1[(size_t)MAXN * MAXF];
__device__ __half g_Ahi[(size_t)MAXN * MAXF];
__device__ __half g_Alo[(size_t)MAXN * MAXF];
__device__ __half g_Chi[(size_t)MAXN * MAXF];
__device__ __half g_Clo[(size_t)MAXN * MAXF];
__device__ __half g_Bhi[(size_t)MAXF * MAXF];
__device__ __half g_Blo[(size_t)MAXF * MAXF];

__device__ __forceinline__ uint32_t smem_u32(const void* p) {
    uint32_t a;
    asm("{ .reg .u64 t; cvta.to.shared.u64 t, %1; cvt.u32.u64 %0, t; }" : "=r"(a) : "l"(p));
    return a;
}
__device__ __forceinline__ void ldsm_x4(uint32_t& r0, uint32_t& r1, uint32_t& r2, uint32_t& r3,
                                        uint32_t addr) {
    asm volatile("ldmatrix.sync.aligned.m8n8.x4.shared.b16 {%0,%1,%2,%3}, [%4];"
                 : "=r"(r0), "=r"(r1), "=r"(r2), "=r"(r3) : "r"(addr));
}
__device__ __forceinline__ void ldsm_x2(uint32_t& r0, uint32_t& r1, uint32_t addr) {
    asm volatile("ldmatrix.sync.aligned.m8n8.x2.shared.b16 {%0,%1}, [%2];"
                 : "=r"(r0), "=r"(r1) : "r"(addr));
}
__device__ __forceinline__ void mma16816(float* c, uint32_t a0, uint32_t a1, uint32_t a2,
                                         uint32_t a3, uint32_t b0, uint32_t b1) {
    asm volatile(
        "mma.sync.aligned.m16n8k16.row.col.f32.f16.f16.f32 "
        "{%0,%1,%2,%3}, {%4,%5,%6,%7}, {%8,%9}, {%0,%1,%2,%3};"
        : "+f"(c[0]), "+f"(c[1]), "+f"(c[2]), "+f"(c[3])
        : "r"(a0), "r"(a1), "r"(a2), "r"(a3), "r"(b0), "r"(b1));
}
__device__ __forceinline__ void cp16(uint32_t saddr, const void* g, bool v) {
    asm volatile("cp.async.cg.shared.global [%0], [%1], 16, %2;"
                 :: "r"(saddr), "l"(g), "r"(v ? 16 : 0) : "memory");
}
__device__ __forceinline__ void cp_commit() {
    asm volatile("cp.async.commit_group;" ::: "memory");
}
template <int NN>
__device__ __forceinline__ void cp_wait() {
    asm volatile("cp.async.wait_group %0;" :: "n"(NN) : "memory");
}
__device__ __forceinline__ __half2 split_hi2(float a, float b, __half2& lo2) {
    __half ha = __float2half_rn(a), hb = __float2half_rn(b);
    lo2 = __halves2half2(__float2half_rn(a - __half2float(ha)),
                         __float2half_rn(b - __half2float(hb)));
    return __halves2half2(ha, hb);
}

// ---------------- preprocessing ----------------
__global__ void zero_indeg_kernel(int n) {
    int i = blockIdx.x * blockDim.x + threadIdx.x;
    if (i < n) g_indeg[i] = 0;
}
__global__ void count_indeg_kernel(const int* __restrict__ dst, int e) {
    int i = blockIdx.x * blockDim.x + threadIdx.x;
    if (i < e) atomicAdd(&g_indeg[dst[i]], 1);
}

// ---- grid-wide 3-phase exclusive scan of g_indeg -> g_offsets/g_cursor ----
__global__ void scan_part_kernel(int n) {
    const int tid = threadIdx.x;
    const int i = blockIdx.x * 256 + tid;
    int v = 0;
    if (i < n) {
        v = g_indeg[i];
        g_dis[i] = rsqrtf((float)(v + 1));   // +1 self-loop
    }
    int r = v;
    const int lane = tid & 31, w = tid >> 5;
    #pragma unroll
    for (int o = 16; o > 0; o >>= 1) r += __shfl_xor_sync(~0u, r, o);
    __shared__ int ws[8];
    if (lane == 0) ws[w] = r;
    __syncthreads();
    if (tid == 0) {
        int s = 0;
        #pragma unroll
        for (int k = 0; k < 8; k++) s += ws[k];
        g_part[blockIdx.x] = s;
    }
}
__global__ void scan_bsum_kernel(int nb, int n) {
    const int tid = threadIdx.x;   // 128
    int v = (tid < nb) ? g_part[tid] : 0;
    const int lane = tid & 31, w = tid >> 5;
    int inc = v;
    #pragma unroll
    for (int o = 1; o < 32; o <<= 1) { int t = __shfl_up_sync(~0u, inc, o); if (lane >= o) inc += t; }
    __shared__ int ws[4];
    if (lane == 31) ws[w] = inc;
    __syncthreads();
    if (tid == 0) {
        int run = 0;
        #pragma unroll
        for (int k = 0; k < 4; k++) { int t = ws[k]; ws[k] = run; run += t; }
    }
    __syncthreads();
    int excl = ws[w] + inc - v;
    if (tid < nb) g_part[tid] = excl;
    if (tid == nb - 1) g_offsets[n] = excl + v;
}
__global__ void scan_emit_kernel(int n) {
    const int tid = threadIdx.x;
    const int i = blockIdx.x * 256 + tid;
    int v = (i < n) ? g_indeg[i] : 0;
    const int lane = tid & 31, w = tid >> 5;
    int inc = v;
    #pragma unroll
    for (int o = 1; o < 32; o <<= 1) { int t = __shfl_up_sync(~0u, inc, o); if (lane >= o) inc += t; }
    __shared__ int ws[8];
    if (lane == 31) ws[w] = inc;
    __syncthreads();
    if (tid == 0) {
        int run = 0;
        #pragma unroll
        for (int k = 0; k < 8; k++) { int t = ws[k]; ws[k] = run; run += t; }
    }
    __syncthreads();
    if (i < n) {
        int off = g_part[blockIdx.x] + ws[w] + inc - v;
        g_offsets[i] = off;
        g_cursor[i]  = off;
    }
}

__global__ void fill_csr_kernel(const int* __restrict__ src, const int* __restrict__ dst, int e) {
    int i = blockIdx.x * blockDim.x + threadIdx.x;
    if (i < e) {
        int s = src[i], d = dst[i];
        int pos = atomicAdd(&g_cursor[d], 1);
        g_csr[pos] = make_int2(s, __float_as_int(g_dis[s] * g_dis[d]));
    }
}

// -------- ALL weights [K,N] row-major -> Bt [N,K] fp16 hi/lo split, ONE kernel --------
__global__ void wsplit_all_kernel(const float* __restrict__ W1, const float* __restrict__ W2,
                                  const float* __restrict__ W3,
                                  __half* __restrict__ bhi, __half* __restrict__ blo) {
    __shared__ float tile[32][33];
    const int b = blockIdx.x;
    const float* W; __half *hi, *lo; int K, N, t;
    if (b < 64)       { W = W1; hi = bhi;          lo = blo;          K = 128; N = 512; t = b; }
    else if (b < 192) { W = W2; hi = bhi + 65536;  lo = blo + 65536;  K = 512; N = 256; t = b - 64; }
    else              { W = W3; hi = bhi + 196608; lo = blo + 196608; K = 256; N = 128; t = b - 192; }
    const int ntx = N >> 5;
    const int bx = (t % ntx) * 32;   // N origin
    const int by = (t / ntx) * 32;   // K origin
    const int tx = threadIdx.x & 31, ty = threadIdx.x >> 5;
    #pragma unroll
    for (int r = 0; r < 32; r += 8)
        tile[ty + r][tx] = W[(size_t)(by + ty + r) * N + bx + tx];
    __syncthreads();
    #pragma unroll
    for (int r = 0; r < 32; r += 8) {
        float f = tile[tx][ty + r];
        __half h = __float2half_rn(f);
        size_t o = (size_t)(bx + ty + r) * K + by + tx;
        hi[o] = h;
        lo[o] = __float2half_rn(f - __half2float(h));
    }
}

// ============ HMMA fp16-split GEMM, cp.async 2-stage pipeline (BM=128) ============
#define BM 128
#define BN 128
#define BK 32
#define ASTR 40                      // halves per row (padded): 80 bytes
#define TILE_B 10240                 // 128*80 bytes per tile
#define STAGE_B (4 * TILE_B)         // AH AL BH BL
#define GEMM_SMEM (2 * STAGE_B)      // 81920 bytes

template <int EPI>
__global__ void __launch_bounds__(256)
gemm_hmma_kernel(const __half* __restrict__ Ahi, const __half* __restrict__ Alo,
                 const __half* __restrict__ Bhi, const __half* __restrict__ Blo,
                 float* __restrict__ Cf, __half* __restrict__ Chi, __half* __restrict__ Clo,
                 const float* __restrict__ bias, int M, int N, int K) {
    extern __shared__ char smem[];
    const uint32_t sb = smem_u32(smem);

    const int tid = threadIdx.x;
    const int lane = tid & 31, wid = tid >> 5;
    const int wm = wid & 1;        // 0..1 (m)
    const int wn = wid >> 1;       // 0..3 (n)
    const int by = blockIdx.y;
    const int n0 = blockIdx.x * BN;

    float acc[4][4][4];
    #pragma unroll
    for (int mt = 0; mt < 4; mt++)
        #pragma unroll
        for (int nt = 0; nt < 4; nt++)
            #pragma unroll
            for (int r = 0; r < 4; r++) acc[mt][nt][r] = 0.f;

    const int a_msel = lane >> 3;
    const int a_rowin = (lane & 7) + ((a_msel & 1) << 3);
    const int a_colin = (a_msel >> 1) << 3;
    const int b_rowin = lane & 7;
    const int b_colin = ((lane >> 3) & 1) << 3;

    const int ldrow = tid >> 2;          // 0..63
    const int ldsegB = (tid & 3) * 16;
    const int ldsegH = (tid & 3) * 8;

    auto load_stage = [&](int s, int k0) {
        const uint32_t st = sb + s * STAGE_B;
        #pragma unroll
        for (int h = 0; h < 2; h++) {
            const int row = ldrow + h * 64;
            const int ar = by * BM + row;
            const bool va = (ar < M);
            const int arc = va ? ar : 0;
            const uint32_t so = st + row * 80 + ldsegB;
            size_t ai = (size_t)arc * K + k0 + ldsegH;
            cp16(so,              Ahi + ai, va);
            cp16(so + TILE_B,     Alo + ai, va);
            size_t bi = (size_t)(n0 + row) * K + k0 + ldsegH;
            cp16(so + 2 * TILE_B, Bhi + bi, true);
            cp16(so + 3 * TILE_B, Blo + bi, true);
        }
        cp_commit();
    };

    const int nc = K / BK;
    load_stage(0, 0);

    for (int c = 0; c < nc; c++) {
        cp_wait<0>();
        __syncthreads();
        if (c + 1 < nc) load_stage((c + 1) & 1, (c + 1) * BK);

        const uint32_t st = sb + (c & 1) * STAGE_B;
        const uint32_t aAh = st;
        const uint32_t aAl = st + TILE_B;
        const uint32_t aBh = st + 2 * TILE_B;
        const uint32_t aBl = st + 3 * TILE_B;

        #pragma unroll
        for (int ks = 0; ks < 2; ks++) {
            uint32_t bh[4][2], bl[4][2];
            #pragma unroll
            for (int nt = 0; nt < 4; nt++) {
                uint32_t boff = ((wn * 32 + nt * 8 + b_rowin) * ASTR + ks * 16 + b_colin) * 2;
                ldsm_x2(bh[nt][0], bh[nt][1], aBh + boff);
                ldsm_x2(bl[nt][0], bl[nt][1], aBl + boff);
            }
            #pragma unroll
            for (int mt = 0; mt < 4; mt++) {
                uint32_t aoff = ((wm * 64 + mt * 16 + a_rowin) * ASTR + ks * 16 + a_colin) * 2;
                uint32_t ah0, ah1, ah2, ah3, al0, al1, al2, al3;
                ldsm_x4(ah0, ah1, ah2, ah3, aAh + aoff);
                ldsm_x4(al0, al1, al2, al3, aAl + aoff);
                #pragma unroll
                for (int nt = 0; nt < 4; nt++) {
                    mma16816(acc[mt][nt], ah0, ah1, ah2, ah3, bh[nt][0], bh[nt][1]);
                    mma16816(acc[mt][nt], ah0, ah1, ah2, ah3, bl[nt][0], bl[nt][1]);
                    mma16816(acc[mt][nt], al0, al1, al2, al3, bh[nt][0], bh[nt][1]);
                }
            }
        }
        __syncthreads();
    }

    const int erow = lane >> 2;
    const int ecol = (lane & 3) << 1;
    #pragma unroll
    for (int mt = 0; mt < 4; mt++) {
        #pragma unroll
        for (int nt = 0; nt < 4; nt++) {
            const int gc = n0 + wn * 32 + nt * 8 + ecol;
            #pragma unroll
            for (int half = 0; half < 2; half++) {
                const int gr = by * BM + wm * 64 + mt * 16 + erow + half * 8;
                if (gr < M) {
                    float v0 = acc[mt][nt][half * 2 + 0];
                    float v1 = acc[mt][nt][half * 2 + 1];
                    if (EPI == 1) {
                        v0 += bias[gc];     v1 += bias[gc + 1];
                        v0 = (v0 > 0.f) ? v0 : 0.15f * v0;
                        v1 = (v1 > 0.f) ? v1 : 0.15f * v1;
                        __half2 lo2;
                        __half2 hi2 = split_hi2(v0, v1, lo2);
                        size_t o = (size_t)gr * N + gc;
                        *(__half2*)(Chi + o) = hi2;
                        *(__half2*)(Clo + o) = lo2;
                    } else {
                        *(float2*)(Cf + (size_t)gr * N + gc) = make_float2(v0, v1);
                    }
                }
            }
        }
    }
}

// ============ BM=64 variant, generalized N tiles: grid (N/128, M/64) ============
#define T64_A 5120                    // 64*80
#define T64_B 10240                   // 128*80
#define STAGE64 (2 * T64_A + 2 * T64_B)   // 30720
#define GEMM64_SMEM (2 * STAGE64)         // 61440

__global__ void __launch_bounds__(256)
gemm_hmma64_kernel(const __half* __restrict__ Ahi, const __half* __restrict__ Alo,
                   const __half* __restrict__ Bhi, const __half* __restrict__ Blo,
                   float* __restrict__ Cf, int M, int N, int K) {
    extern __shared__ char smem[];
    const uint32_t sb = smem_u32(smem);

    const int tid = threadIdx.x;
    const int lane = tid & 31, wid = tid >> 5;   // wn = wid (0..7), 16 cols each
    const int by = blockIdx.y;                   // 64-row tile
    const int n0 = blockIdx.x * 128;             // 128-col tile

    float acc[4][2][4];
    #pragma unroll
    for (int mt = 0; mt < 4; mt++)
        #pragma unroll
        for (int nt = 0; nt < 2; nt++)
            #pragma unroll
            for (int r = 0; r < 4; r++) acc[mt][nt][r] = 0.f;

    const int a_msel = lane >> 3;
    const int a_rowin = (lane & 7) + ((a_msel & 1) << 3);
    const int a_colin = (a_msel >> 1) << 3;
    const int b_rowin = lane & 7;
    const int b_colin = ((lane >> 3) & 1) << 3;

    const int ldrow = tid >> 2;          // 0..63
    const int ldsegB = (tid & 3) * 16;
    const int ldsegH = (tid & 3) * 8;

    auto load_stage = [&](int s, int k0) {
        const uint32_t st = sb + s * STAGE64;
        {
            const int ar = by * 64 + ldrow;
            const bool va = (ar < M);
            const int arc = va ? ar : 0;
            const uint32_t so = st + ldrow * 80 + ldsegB;
            size_t ai = (size_t)arc * K + k0 + ldsegH;
            cp16(so,         Ahi + ai, va);
            cp16(so + T64_A, Alo + ai, va);
        }
        #pragma unroll
        for (int h = 0; h < 2; h++) {
            const int row = ldrow + h * 64;
            const uint32_t so = st + 2 * T64_A + row * 80 + ldsegB;
            size_t bi = (size_t)(n0 + row) * K + k0 + ldsegH;
            cp16(so,         Bhi + bi, true);
            cp16(so + T64_B, Blo + bi, true);
        }
        cp_commit();
    };

    const int nc = K / BK;
    load_stage(0, 0);

    for (int c = 0; c < nc; c++) {
        cp_wait<0>();
        __syncthreads();
        if (c + 1 < nc) load_stage((c + 1) & 1, (c + 1) * BK);

        const uint32_t st = sb + (c & 1) * STAGE64;
        const uint32_t aAh = st;
        const uint32_t aAl = st + T64_A;
        const uint32_t aBh = st + 2 * T64_A;
        const uint32_t aBl = st + 2 * T64_A + T64_B;

        #pragma unroll
        for (int ks = 0; ks < 2; ks++) {
            uint32_t bh[2][2], bl[2][2];
            #pragma unroll
            for (int nt = 0; nt < 2; nt++) {
                uint32_t boff = ((wid * 16 + nt * 8 + b_rowin) * ASTR + ks * 16 + b_colin) * 2;
                ldsm_x2(bh[nt][0], bh[nt][1], aBh + boff);
                ldsm_x2(bl[nt][0], bl[nt][1], aBl + boff);
            }
            #pragma unroll
            for (int mt = 0; mt < 4; mt++) {
                uint32_t aoff = ((mt * 16 + a_rowin) * ASTR + ks * 16 + a_colin) * 2;
                uint32_t ah0, ah1, ah2, ah3, al0, al1, al2, al3;
                ldsm_x4(ah0, ah1, ah2, ah3, aAh + aoff);
                ldsm_x4(al0, al1, al2, al3, aAl + aoff);
                #pragma unroll
                for (int nt = 0; nt < 2; nt++) {
                    mma16816(acc[mt][nt], ah0, ah1, ah2, ah3, bh[nt][0], bh[nt][1]);
                    mma16816(acc[mt][nt], ah0, ah1, ah2, ah3, bl[nt][0], bl[nt][1]);
                    mma16816(acc[mt][nt], al0, al1, al2, al3, bh[nt][0], bh[nt][1]);
                }
            }
        }
        __syncthreads();
    }

    const int erow = lane >> 2;
    const int ecol = (lane & 3) << 1;
    #pragma unroll
    for (int mt = 0; mt < 4; mt++) {
        #pragma unroll
        for (int nt = 0; nt < 2; nt++) {
            const int gc = n0 + wid * 16 + nt * 8 + ecol;
            #pragma unroll
            for (int half = 0; half < 2; half++) {
                const int gr = by * 64 + mt * 16 + erow + half * 8;
                if (gr < M) {
                    *(float2*)(Cf + (size_t)gr * N + gc) =
                        make_float2(acc[mt][nt][half * 2 + 0], acc[mt][nt][half * 2 + 1]);
                }
            }
        }
    }
}

// ------- aggregation (warp per node, float4): out = [lrelu(]sum + self[+bias)] -------
template <int F, int OUT_SPLIT, int BIASACT>
__global__ void __launch_bounds__(256)
agg_warp_kernel(const float* __restrict__ h, float* __restrict__ outf,
                __half* __restrict__ ohi, __half* __restrict__ olo,
                const float* __restrict__ bias, int n) {
    const int gw = (blockIdx.x * blockDim.x + threadIdx.x) >> 5;
    const int lane = threadIdx.x & 31;
    if (gw >= n) return;
    constexpr int V = F / 128;

    float4 acc[V];
    const float di = g_dis[gw];
    const float selfw = di * di;
    const float4* hrow = (const float4*)(h + (size_t)gw * F);
    #pragma unroll
    for (int v = 0; v < V; v++) {
        float4 t = hrow[lane + 32 * v];
        acc[v] = make_float4(selfw * t.x, selfw * t.y, selfw * t.z, selfw * t.w);
    }

    const int beg = g_offsets[gw];
    const int end = g_offsets[gw + 1];
    for (int j = beg; j < end; j++) {
        const int2  c = g_csr[j];
        const int   s = c.x;
        const float w = __int_as_float(c.y);
        const float4* hs = (const float4*)(h + (size_t)s * F);
        #pragma unroll
        for (int v = 0; v < V; v++) {
            float4 t = hs[lane + 32 * v];
            acc[v].x += w * t.x; acc[v].y += w * t.y;
            acc[v].z += w * t.z; acc[v].w += w * t.w;
        }
    }

    #pragma unroll
    for (int v = 0; v < V; v++) {
        float4 r = acc[v];
        if (BIASACT) {
            const float4 b = ((const float4*)bias)[lane + 32 * v];
            r.x += b.x; r.y += b.y; r.z += b.z; r.w += b.w;
            r.x = (r.x > 0.f) ? r.x : 0.15f * r.x;
            r.y = (r.y > 0.f) ? r.y : 0.15f * r.y;
            r.z = (r.z > 0.f) ? r.z : 0.15f * r.z;
            r.w = (r.w > 0.f) ? r.w : 0.15f * r.w;
        }
        const size_t o = (size_t)gw * F + (lane + 32 * v) * 4;
        if (OUT_SPLIT) {
            __half2 lo0, lo1;
            __half2 hi0 = split_hi2(r.x, r.y, lo0);
            __half2 hi1 = split_hi2(r.z, r.w, lo1);
            *(__half2*)(ohi + o)     = hi0;
            *(__half2*)(ohi + o + 2) = hi1;
            *(__half2*)(olo + o)     = lo0;
            *(__half2*)(olo + o + 2) = lo1;
        } else {
            *(float4*)(outf + o) = r;
        }
    }
}

// ---------------- fused head: h(128) -> 16 -> lrelu(32) -> 2 ----------------
__global__ __launch_bounds__(256)
void head_kernel(const float* __restrict__ h,
                 const float* __restrict__ Wp,  const float* __restrict__ bp,
                 const float* __restrict__ Wf1, const float* __restrict__ bf1,
                 const float* __restrict__ Wf2, const float* __restrict__ bf2,
                 float* __restrict__ out, int n) {
    __shared__ float sWp[128 * 16];
    __shared__ float sWf1[16 * 32];
    __shared__ float sWf2[32 * 2];
    __shared__ float sbp[16], sbf1[32], sbf2[2];

    for (int i = threadIdx.x; i < 128 * 16; i += 256) sWp[i] = Wp[i];
    for (int i = threadIdx.x; i < 16 * 32;  i += 256) sWf1[i] = Wf1[i];
    if (threadIdx.x < 64) sWf2[threadIdx.x] = Wf2[threadIdx.x];
    if (threadIdx.x < 16) sbp[threadIdx.x]  = bp[threadIdx.x];
    if (threadIdx.x < 32) sbf1[threadIdx.x] = bf1[threadIdx.x];
    if (threadIdx.x < 2)  sbf2[threadIdx.x] = bf2[threadIdx.x];
    __syncthreads();

    const int warp = threadIdx.x / 32, lane = threadIdx.x % 32;
    const int node = blockIdx.x * 8 + warp;
    if (node >= n) return;

    float hv[4];
    const float* hr = h + (size_t)node * 128;
    #pragma unroll
    for (int k = 0; k < 4; k++) hv[k] = hr[lane + 32 * k];

    float s16[16];
    #pragma unroll
    for (int j = 0; j < 16; j++) {
        float p = 0.f;
        #pragma unroll
        for (int k = 0; k < 4; k++) p += hv[k] * sWp[(lane + 32 * k) * 16 + j];
        #pragma unroll
        for (int o = 16; o > 0; o >>= 1) p += __shfl_xor_sync(0xffffffffu, p, o);
        s16[j] = p + sbp[j];
    }

    float tv = sbf1[lane];
    #pragma unroll
    for (int k = 0; k < 16; k++) tv += s16[k] * sWf1[k * 32 + lane];
    tv = (tv > 0.f) ? tv : 0.15f * tv;

    float v0 = tv * sWf2[lane * 2 + 0];
    float v1 = tv * sWf2[lane * 2 + 1];
    #pragma unroll
    for (int o = 16; o > 0; o >>= 1) {
        v0 += __shfl_xor_sync(0xffffffffu, v0, o);
        v1 += __shfl_xor_sync(0xffffffffu, v1, o);
    }
    if (lane == 0) {
        out[(size_t)node * 2 + 0] = v0 + sbf2[0];
        out[(size_t)node * 2 + 1] = v1 + sbf2[1];
    }
}

// ---------------- launch ----------------
extern "C" void kernel_launch(void* const* d_in, const int* in_sizes, int n_in,
                              void* d_out, int out_size) {
    const float* x   = (const float*)d_in[0];
    const int*   ei  = (const int*)  d_in[1];
    const float* W1  = (const float*)d_in[3];
    const float* b1  = (const float*)d_in[4];
    const float* W2  = (const float*)d_in[5];
    const float* b2  = (const float*)d_in[6];
    const float* W3  = (const float*)d_in[7];
    const float* b3  = (const float*)d_in[8];
    const float* Wp  = (const float*)d_in[9];
    const float* bp  = (const float*)d_in[10];
    const float* Wf1 = (const float*)d_in[11];
    const float* bf1 = (const float*)d_in[12];
    const float* Wf2 = (const float*)d_in[13];
    const float* bf2 = (const float*)d_in[14];
    float* out = (float*)d_out;

    const int N = in_sizes[0] / 128;
    const int E = in_sizes[1] / 2;
    const int* src = ei;
    const int* dst = ei + E;

    float *h0, *h1;
    __half *ahi, *alo, *chi, *clo, *bhi, *blo;
    cudaGetSymbolAddress((void**)&h0, g_h0);
    cudaGetSymbolAddress((void**)&h1, g_h1);
    cudaGetSymbolAddress((void**)&ahi, g_Ahi);
    cudaGetSymbolAddress((void**)&alo, g_Alo);
    cudaGetSymbolAddress((void**)&chi, g_Chi);
    cudaGetSymbolAddress((void**)&clo, g_Clo);
    cudaGetSymbolAddress((void**)&bhi, g_Bhi);
    cudaGetSymbolAddress((void**)&blo, g_Blo);

    __half *b1hi = bhi,          *b1lo = blo;            // 128*512
    __half *b2hi = bhi + 65536,  *b2lo = blo + 65536;    // 512*256
    __half *b3hi = bhi + 196608, *b3lo = blo + 196608;   // 256*128

    cudaFuncSetAttribute(gemm_hmma_kernel<0>,
                         cudaFuncAttributeMaxDynamicSharedMemorySize, GEMM_SMEM);
    cudaFuncSetAttribute(gemm_hmma_kernel<1>,
                         cudaFuncAttributeMaxDynamicSharedMemorySize, GEMM_SMEM);
    cudaFuncSetAttribute(gemm_hmma64_kernel,
                         cudaFuncAttributeMaxDynamicSharedMemorySize, GEMM64_SMEM);

    const int GM = (N + 127) / 128;
    const int GM64 = (N + 63) / 64;
    const int AGG_BLK = (N * 32 + 255) / 256;
    const int NB = (N + 255) / 256;   // scan blocks (<=128)

    // --- preprocessing ---
    zero_indeg_kernel<<<(N + 255) / 256, 256>>>(N);
    count_indeg_kernel<<<(E + 255) / 256, 256>>>(dst, E);
    scan_part_kernel<<<NB, 256>>>(N);
    scan_bsum_kernel<<<1, 128>>>(NB, N);
    scan_emit_kernel<<<NB, 256>>>(N);
    fill_csr_kernel<<<(E + 255) / 256, 256>>>(src, dst, E);

    // --- layer 1 (aggregate-first): split(agg(x)) -> gemm(+bias+lrelu, split out) ---
    agg_warp_kernel<128, 1, 0><<<AGG_BLK, 256>>>(x, nullptr, ahi, alo, nullptr, N);
    wsplit_all_kernel<<<224, 256>>>(W1, W2, W3, bhi, blo);
    {
        dim3 grid(512 / 128, GM);
        gemm_hmma_kernel<1><<<grid, 256, GEMM_SMEM>>>(ahi, alo, b1hi, b1lo, nullptr,
                                                      chi, clo, b1, N, 512, 128);
    }
    // --- layer 2: BM=64 gemm -> agg(+bias+lrelu, split) ---
    {
        dim3 grid(256 / 128, GM64);
        gemm_hmma64_kernel<<<grid, 256, GEMM64_SMEM>>>(chi, clo, b2hi, b2lo, h0,
                                                       N, 256, 512);
        agg_warp_kernel<256, 1, 1><<<AGG_BLK, 256>>>(h0, nullptr, ahi, alo, b2, N);
    }
    // --- layer 3: BM=64 gemm -> agg(+bias+lrelu, fp32) -> head ---
    {
        dim3 grid(1, GM64);
        gemm_hmma64_kernel<<<grid, 256, GEMM64_SMEM>>>(ahi, alo, b3hi, b3lo, h0,
                                                       N, 128, 256);
        agg_warp_kernel<128, 0, 1><<<AGG_BLK, 256>>>(h0, h1, nullptr, nullptr, b3, N);
    }
    head_kernel<<<(N + 7) / 8, 256>>>(h1, Wp, bp, Wf1, bf1, Wf2, bf2, out, N);
}